// round 15
// baseline (speedup 1.0000x reference)
#include <cuda_runtime.h>
#include <cuda_fp16.h>
#include <cstdint>

// ---------------------------------------------------------------------------
// WordGraphNet: 2-layer weighted GraphConv — single persistent megakernel.
//   Phase A: bucket build (blocks 0..FILL_BLKS) || gemm128 (rest)
//   Phase B: aggregate1 (+norm+leaky) -> h1 fp16
//   Phase C: gemm64 (tensor cores)
//   Phase D: aggregate2 (+norm) -> out fp32; resets cnt for next replay
// Grid barriers between phases; 296 blocks (2/SM) all co-resident.
// ---------------------------------------------------------------------------

#define MAX_NODES 50000
#define MAX_EDGES 1200000
#define HID 64
#define NEG_SLOPE 0.01f
#define BCAP 96

#define TILE_M 128
#define LDA 72
#define LDB 72

#define NBLK 296
#define FILL_BLKS 112

typedef unsigned long long ull;

__device__ __half g_Wh[MAX_NODES * HID];        // projected features (fp16)
__device__ __half g_h1[MAX_NODES * HID];        // layer-1 output (fp16)
__device__ int    g_cnt[MAX_NODES];             // degree (zeroed by phase D)
__device__ int2   g_bucket[MAX_NODES * BCAP];   // {src, float_bits(w)} per dst
__device__ int    g_bar_count;
__device__ volatile int g_bar_gen;

__device__ __forceinline__ float leaky(float v) {
    return v > 0.f ? v : NEG_SLOPE * v;
}
__device__ __forceinline__ uint32_t smem_u32(const void* p) {
    return (uint32_t)__cvta_generic_to_shared(p);
}
__device__ __forceinline__ void ldm_x4(uint32_t& r0, uint32_t& r1,
                                       uint32_t& r2, uint32_t& r3, uint32_t addr) {
    asm volatile("ldmatrix.sync.aligned.m8n8.x4.shared.b16 {%0,%1,%2,%3}, [%4];"
                 : "=r"(r0), "=r"(r1), "=r"(r2), "=r"(r3) : "r"(addr));
}
__device__ __forceinline__ void ldm_x4_trans(uint32_t& r0, uint32_t& r1,
                                             uint32_t& r2, uint32_t& r3, uint32_t addr) {
    asm volatile("ldmatrix.sync.aligned.m8n8.x4.trans.shared.b16 {%0,%1,%2,%3}, [%4];"
                 : "=r"(r0), "=r"(r1), "=r"(r2), "=r"(r3) : "r"(addr));
}
__device__ __forceinline__ void mma16816(float* d,
                                         uint32_t a0, uint32_t a1, uint32_t a2, uint32_t a3,
                                         uint32_t b0, uint32_t b1) {
    asm volatile(
        "mma.sync.aligned.m16n8k16.row.col.f32.f16.f16.f32 "
        "{%0,%1,%2,%3}, {%4,%5,%6,%7}, {%8,%9}, {%0,%1,%2,%3};"
        : "+f"(d[0]), "+f"(d[1]), "+f"(d[2]), "+f"(d[3])
        : "r"(a0), "r"(a1), "r"(a2), "r"(a3), "r"(b0), "r"(b1));
}

// Grid-wide barrier: all NBLK blocks are co-resident by construction.
__device__ __forceinline__ void grid_barrier() {
    __syncthreads();
    if (threadIdx.x == 0) {
        __threadfence();                       // release phase writes
        int gen = g_bar_gen;
        asm volatile("" ::: "memory");
        if (atomicAdd(&g_bar_count, 1) == NBLK - 1) {
            g_bar_count = 0;
            __threadfence();
            g_bar_gen = gen + 1;
        } else {
            while (g_bar_gen == gen) __nanosleep(64);
        }
        __threadfence();                       // acquire
    }
    __syncthreads();
}

// ---------------------------------------------------------------------------
// GEMM building blocks (identical math to the proven standalone kernel)
// ---------------------------------------------------------------------------
template <int K>
__device__ __forceinline__ void stage_B(const float* __restrict__ Wg,
                                        __half* Bs, int tid) {
    for (int f = tid; f < K * 16; f += 256) {
        int k = f >> 4, j = f & 15;
        float4 w4 = __ldg(reinterpret_cast<const float4*>(Wg) + f);
        uint2 p;
        *reinterpret_cast<__half2*>(&p.x) = __floats2half2_rn(w4.x, w4.y);
        *reinterpret_cast<__half2*>(&p.y) = __floats2half2_rn(w4.z, w4.w);
        *reinterpret_cast<uint2*>(Bs + k * LDB + j * 4) = p;
    }
}

template <int K, bool FP16_IN>
__device__ void gemm_tile(int tile, const void* __restrict__ Hv,
                          const float* __restrict__ bg,
                          __half* __restrict__ out, int n_nodes,
                          __half* As, const __half* Bs) {
    const int tid = threadIdx.x;
    const int lane = tid & 31;
    const int warp = tid >> 5;
    const int node0 = tile * TILE_M;

    float d[8][4];
#pragma unroll
    for (int j = 0; j < 8; j++)
#pragma unroll
        for (int q = 0; q < 4; q++) d[j][q] = 0.f;

#pragma unroll
    for (int kc0 = 0; kc0 < K; kc0 += 64) {
        if (FP16_IN) {
            const __half* H = (const __half*)Hv;
#pragma unroll
            for (int f = tid; f < TILE_M * 8; f += 256) {
                int m = f >> 3, j = f & 7;
                int node = node0 + m;
                uint4 v = make_uint4(0u, 0u, 0u, 0u);
                if (node < n_nodes)
                    v = __ldg(reinterpret_cast<const uint4*>(
                        H + (size_t)node * K + kc0) + j);
                *reinterpret_cast<uint4*>(As + m * LDA + j * 8) = v;
            }
        } else {
            const float* H = (const float*)Hv;
#pragma unroll
            for (int f = tid; f < TILE_M * 16; f += 256) {
                int m = f >> 4, j = f & 15;
                int node = node0 + m;
                float4 v = make_float4(0.f, 0.f, 0.f, 0.f);
                if (node < n_nodes)
                    v = __ldg(reinterpret_cast<const float4*>(
                        H + (size_t)node * K + kc0) + j);
                uint2 p;
                *reinterpret_cast<__half2*>(&p.x) = __floats2half2_rn(v.x, v.y);
                *reinterpret_cast<__half2*>(&p.y) = __floats2half2_rn(v.z, v.w);
                *reinterpret_cast<uint2*>(As + m * LDA + j * 4) = p;
            }
        }
        __syncthreads();

#pragma unroll
        for (int ks = 0; ks < 4; ks++) {
            uint32_t a0, a1, a2, a3;
            uint32_t aaddr = smem_u32(
                As + (warp * 16 + (lane & 15)) * LDA + ks * 16 + (lane >> 4) * 8);
            ldm_x4(a0, a1, a2, a3, aaddr);
#pragma unroll
            for (int jp = 0; jp < 4; jp++) {
                uint32_t b0, b1, b2, b3;
                uint32_t baddr = smem_u32(
                    Bs + (kc0 + ks * 16 + (lane & 15)) * LDB + jp * 16 + (lane >> 4) * 8);
                ldm_x4_trans(b0, b1, b2, b3, baddr);
                mma16816(d[2 * jp],     a0, a1, a2, a3, b0, b1);
                mma16816(d[2 * jp + 1], a0, a1, a2, a3, b2, b3);
            }
        }
        __syncthreads();   // As reused next chunk / next tile
    }

    int r  = lane >> 2;
    int cb = (lane & 3) * 2;
    int node_lo = node0 + warp * 16 + r;
    int node_hi = node_lo + 8;
#pragma unroll
    for (int j = 0; j < 8; j++) {
        float bx = __ldg(bg + 8 * j + cb);
        float by = __ldg(bg + 8 * j + cb + 1);
        __half2 lo = __floats2half2_rn(d[j][0] + bx, d[j][1] + by);
        __half2 hi = __floats2half2_rn(d[j][2] + bx, d[j][3] + by);
        if (node_lo < n_nodes)
            *reinterpret_cast<__half2*>(out + (size_t)node_lo * HID + 8 * j + cb) = lo;
        if (node_hi < n_nodes)
            *reinterpret_cast<__half2*>(out + (size_t)node_hi * HID + 8 * j + cb) = hi;
    }
}

// ---------------------------------------------------------------------------
// Aggregate phase: node per warp, block-stride; 32 lanes split-K over chunks.
// ---------------------------------------------------------------------------
template <bool DO_LEAKY, bool FP16_OUT, bool RESET_CNT>
__device__ void agg_phase(const uint2* __restrict__ Whh,
                          const int2* __restrict__ bucket,
                          int* __restrict__ cnt,
                          void* __restrict__ outv,
                          int n_nodes, int bid, int tid) {
    int warp = tid >> 5;
    int lane = tid & 31;
    int half = lane >> 4;
    int c4 = lane & 15;

    for (int node = bid * 8 + warp; node < n_nodes; node += NBLK * 8) {
        int degi = min(cnt[node], BCAP);
        float deg = (float)degi;
        const int2* bk = bucket + (size_t)node * BCAP;

        float4 acc = make_float4(0.f, 0.f, 0.f, 0.f);

        for (int e = half * 8; e < degi; e += 16) {
            int2 c[8];
#pragma unroll
            for (int j = 0; j < 8; j++)
                c[j] = __ldg(bk + min(e + j, degi - 1));

            uint2 v[8];
#pragma unroll
            for (int j = 0; j < 8; j++)
                v[j] = __ldg(Whh + (size_t)c[j].x * 16 + c4);

#pragma unroll
            for (int j = 0; j < 8; j++) {
                float w = (e + j < degi) ? __int_as_float(c[j].y) : 0.f;
                float2 lo = __half22float2(*reinterpret_cast<__half2*>(&v[j].x));
                float2 hi = __half22float2(*reinterpret_cast<__half2*>(&v[j].y));
                acc.x += lo.x * w;
                acc.y += lo.y * w;
                acc.z += hi.x * w;
                acc.w += hi.y * w;
            }
        }

        acc.x += __shfl_xor_sync(0xffffffffu, acc.x, 16);
        acc.y += __shfl_xor_sync(0xffffffffu, acc.y, 16);
        acc.z += __shfl_xor_sync(0xffffffffu, acc.z, 16);
        acc.w += __shfl_xor_sync(0xffffffffu, acc.w, 16);

        if (half == 0) {
            float inv = 1.0f / fmaxf(deg, 1.0f);
            acc.x *= inv; acc.y *= inv; acc.z *= inv; acc.w *= inv;
            if (DO_LEAKY) {
                acc.x = leaky(acc.x); acc.y = leaky(acc.y);
                acc.z = leaky(acc.z); acc.w = leaky(acc.w);
            }
            if (FP16_OUT) {
                uint2 p;
                *reinterpret_cast<__half2*>(&p.x) = __floats2half2_rn(acc.x, acc.y);
                *reinterpret_cast<__half2*>(&p.y) = __floats2half2_rn(acc.z, acc.w);
                reinterpret_cast<uint2*>(outv)[(size_t)node * 16 + c4] = p;
            } else {
                reinterpret_cast<float4*>(outv)[(size_t)node * 16 + c4] = acc;
            }
            if (RESET_CNT && c4 == 0) cnt[node] = 0;   // ready for next replay
        }
    }
}

// ---------------------------------------------------------------------------
// The megakernel
// ---------------------------------------------------------------------------
__global__ __launch_bounds__(256, 2)
void wgn_megakernel(const float* __restrict__ x,
                    const float* __restrict__ ew,
                    const float* __restrict__ W1,
                    const float* __restrict__ b1,
                    const float* __restrict__ W2,
                    const float* __restrict__ b2,
                    const int* __restrict__ src,
                    const int* __restrict__ dst,
                    float* __restrict__ out,
                    int n_nodes, int n_edges) {
    __shared__ __half As[TILE_M * LDA];   // 18432 B
    __shared__ __half Bs[128 * LDB];      // 18432 B

    const int tid = threadIdx.x;
    const int bid = blockIdx.x;
    const int ntiles = (n_nodes + TILE_M - 1) / TILE_M;

    // ---- Phase A: bucket build || layer-1 projection ----
    if (bid < FILL_BLKS) {
        for (int e = bid * 256 + tid; e < n_edges; e += FILL_BLKS * 256) {
            int d = __ldg(dst + e);
            int pos = atomicAdd(g_cnt + d, 1);
            if (pos < BCAP)
                g_bucket[(size_t)d * BCAP + pos] =
                    make_int2(__ldg(src + e), __float_as_int(__ldg(ew + e)));
        }
    } else {
        stage_B<128>(W1, Bs, tid);
        __syncthreads();
        for (int t = bid - FILL_BLKS; t < ntiles; t += NBLK - FILL_BLKS)
            gemm_tile<128, false>(t, x, b1, g_Wh, n_nodes, As, Bs);
    }
    grid_barrier();

    // ---- Phase B: aggregate 1 -> h1 (fp16, leaky fused) ----
    agg_phase<true, true, false>((const uint2*)g_Wh, g_bucket, g_cnt,
                                 g_h1, n_nodes, bid, tid);
    grid_barrier();

    // ---- Phase C: layer-2 projection ----
    stage_B<64>(W2, Bs, tid);
    __syncthreads();
    for (int t = bid; t < ntiles; t += NBLK)
        gemm_tile<64, true>(t, g_h1, b2, g_Wh, n_nodes, As, Bs);
    grid_barrier();

    // ---- Phase D: aggregate 2 -> out (fp32), reset cnt ----
    agg_phase<false, false, true>((const uint2*)g_Wh, g_bucket, g_cnt,
                                  out, n_nodes, bid, tid);
}

// ---------------------------------------------------------------------------
// Launch: one kernel, one graph node.
// ---------------------------------------------------------------------------
extern "C" void kernel_launch(void* const* d_in, const int* in_sizes, int n_in,
                              void* d_out, int out_size) {
    const float* x   = (const float*)d_in[0];
    const float* ew  = (const float*)d_in[1];
    const float* W1  = (const float*)d_in[2];
    const float* b1  = (const float*)d_in[3];
    const float* W2  = (const float*)d_in[4];
    const float* b2  = (const float*)d_in[5];
    const int*   src = (const int*)d_in[6];
    const int*   dst = (const int*)d_in[7];
    float*       out = (float*)d_out;

    int n_nodes = in_sizes[0] / 128;
    int n_edges = in_sizes[1];

    wgn_megakernel<<<NBLK, 256>>>(x, ew, W1, b1, W2, b2, src, dst,
                                  out, n_nodes, n_edges);
}

// round 16
// speedup vs baseline: 1.3584x; 1.3584x over previous
#include <cuda_runtime.h>
#include <cuda_fp16.h>
#include <cstdint>

// ---------------------------------------------------------------------------
// WordGraphNet: 2-layer weighted GraphConv, bucketed pull-side aggregation.
//   layer(h,W,b): Wh = h@W + b ; s = segsum(Wh[src]*ew, dst) ; out = s/max(deg,1)
//   out = layer2( leaky_relu(layer1(x)) )
// GEMMs on tensor cores (mma.sync m16n8k16, 64-wide K chunks -> gemm64 has a
// single staging sync). Wh/h1 fp16. Bucket edge grouping (one pass, no scan)
// overlapped with layer-1 GEMM via forked capture stream. (R13 structure.)
// ---------------------------------------------------------------------------

#define MAX_NODES 50000
#define MAX_EDGES 1200000
#define HID 64
#define NEG_SLOPE 0.01f
#define BCAP 96

#define TILE_M 128
#define LDA 72   // halves; 144B pitch, 16B-aligned, conflict-free ldmatrix
#define LDB 72

typedef unsigned long long ull;

__device__ __half g_Wh[MAX_NODES * HID];
__device__ __half g_h1[MAX_NODES * HID];
__device__ int    g_cnt[MAX_NODES];
__device__ int2   g_bucket[MAX_NODES * BCAP];

static cudaStream_t g_side = nullptr;
static cudaEvent_t  g_ev_fork = nullptr, g_ev_join = nullptr;
struct _StreamInit {
    _StreamInit() {
        cudaStreamCreateWithFlags(&g_side, cudaStreamNonBlocking);
        cudaEventCreateWithFlags(&g_ev_fork, cudaEventDisableTiming);
        cudaEventCreateWithFlags(&g_ev_join, cudaEventDisableTiming);
    }
};
static _StreamInit g_stream_init;

__device__ __forceinline__ float leaky(float v) {
    return v > 0.f ? v : NEG_SLOPE * v;
}
__device__ __forceinline__ uint32_t smem_u32(const void* p) {
    return (uint32_t)__cvta_generic_to_shared(p);
}
__device__ __forceinline__ void ldm_x4(uint32_t& r0, uint32_t& r1,
                                       uint32_t& r2, uint32_t& r3, uint32_t addr) {
    asm volatile("ldmatrix.sync.aligned.m8n8.x4.shared.b16 {%0,%1,%2,%3}, [%4];"
                 : "=r"(r0), "=r"(r1), "=r"(r2), "=r"(r3) : "r"(addr));
}
__device__ __forceinline__ void ldm_x4_trans(uint32_t& r0, uint32_t& r1,
                                             uint32_t& r2, uint32_t& r3, uint32_t addr) {
    asm volatile("ldmatrix.sync.aligned.m8n8.x4.trans.shared.b16 {%0,%1,%2,%3}, [%4];"
                 : "=r"(r0), "=r"(r1), "=r"(r2), "=r"(r3) : "r"(addr));
}
__device__ __forceinline__ void mma16816(float* d,
                                         uint32_t a0, uint32_t a1, uint32_t a2, uint32_t a3,
                                         uint32_t b0, uint32_t b1) {
    asm volatile(
        "mma.sync.aligned.m16n8k16.row.col.f32.f16.f16.f32 "
        "{%0,%1,%2,%3}, {%4,%5,%6,%7}, {%8,%9}, {%0,%1,%2,%3};"
        : "+f"(d[0]), "+f"(d[1]), "+f"(d[2]), "+f"(d[3])
        : "r"(a0), "r"(a1), "r"(a2), "r"(a3), "r"(b0), "r"(b1));
}

// ---------------------------------------------------------------------------
// Bucket build: one pass. cnt must be zeroed first.
// ---------------------------------------------------------------------------
__global__ void fill_bucket_kernel(const int* __restrict__ src,
                                   const int* __restrict__ dst,
                                   const float* __restrict__ ew,
                                   int* __restrict__ cnt,
                                   int2* __restrict__ bucket,
                                   int n_edges) {
    int e = blockIdx.x * blockDim.x + threadIdx.x;
    if (e >= n_edges) return;
    int d = __ldg(dst + e);
    int pos = atomicAdd(cnt + d, 1);
    if (pos < BCAP)
        bucket[(size_t)d * BCAP + pos] =
            make_int2(__ldg(src + e), __float_as_int(__ldg(ew + e)));
}

// ---------------------------------------------------------------------------
// Tensor-core GEMM + bias: out[n][64] = H[n][K] @ W[K][64] + b, fp16 out.
// 256 threads / 8 warps; warp owns 16 nodes x 64 cols. K chunked by 64:
// K=64 -> single chunk, one staging sync total.
// ---------------------------------------------------------------------------
template <int K, bool FP16_IN>
__global__ __launch_bounds__(256)
void gemm_mma_kernel(const void* __restrict__ Hv,
                     const float* __restrict__ Wg,
                     const float* __restrict__ bg,
                     __half* __restrict__ out,
                     int n_nodes) {
    __shared__ __half As[TILE_M * LDA];   // 18432 B
    __shared__ __half Bs[K * LDB];        // K=128: 18432 B

    const int tid = threadIdx.x;
    const int lane = tid & 31;
    const int warp = tid >> 5;
    const int node0 = blockIdx.x * TILE_M;

    // --- stage W (fp32 -> fp16), K x 64, row pitch LDB ---
    for (int f = tid; f < K * 16; f += 256) {
        int k = f >> 4, j = f & 15;
        float4 w4 = __ldg(reinterpret_cast<const float4*>(Wg) + f);
        uint2 p;
        *reinterpret_cast<__half2*>(&p.x) = __floats2half2_rn(w4.x, w4.y);
        *reinterpret_cast<__half2*>(&p.y) = __floats2half2_rn(w4.z, w4.w);
        *reinterpret_cast<uint2*>(Bs + k * LDB + j * 4) = p;
    }

    float d[8][4];
#pragma unroll
    for (int j = 0; j < 8; j++)
#pragma unroll
        for (int q = 0; q < 4; q++) d[j][q] = 0.f;

#pragma unroll
    for (int kc0 = 0; kc0 < K; kc0 += 64) {
        // --- stage A chunk: 128 rows x 64 halves, pitch LDA ---
        if (FP16_IN) {
            const __half* H = (const __half*)Hv;
#pragma unroll
            for (int f = tid; f < TILE_M * 8; f += 256) {
                int m = f >> 3, j = f & 7;
                int node = node0 + m;
                uint4 v = make_uint4(0u, 0u, 0u, 0u);
                if (node < n_nodes)
                    v = __ldg(reinterpret_cast<const uint4*>(
                        H + (size_t)node * K + kc0) + j);
                *reinterpret_cast<uint4*>(As + m * LDA + j * 8) = v;
            }
        } else {
            const float* H = (const float*)Hv;
#pragma unroll
            for (int f = tid; f < TILE_M * 16; f += 256) {
                int m = f >> 4, j = f & 15;
                int node = node0 + m;
                float4 v = make_float4(0.f, 0.f, 0.f, 0.f);
                if (node < n_nodes)
                    v = __ldg(reinterpret_cast<const float4*>(
                        H + (size_t)node * K + kc0) + j);
                uint2 p;
                *reinterpret_cast<__half2*>(&p.x) = __floats2half2_rn(v.x, v.y);
                *reinterpret_cast<__half2*>(&p.y) = __floats2half2_rn(v.z, v.w);
                *reinterpret_cast<uint2*>(As + m * LDA + j * 4) = p;
            }
        }
        __syncthreads();

#pragma unroll
        for (int ks = 0; ks < 4; ks++) {
            uint32_t a0, a1, a2, a3;
            uint32_t aaddr = smem_u32(
                As + (warp * 16 + (lane & 15)) * LDA + ks * 16 + (lane >> 4) * 8);
            ldm_x4(a0, a1, a2, a3, aaddr);
#pragma unroll
            for (int jp = 0; jp < 4; jp++) {
                uint32_t b0, b1, b2, b3;
                uint32_t baddr = smem_u32(
                    Bs + (kc0 + ks * 16 + (lane & 15)) * LDB + jp * 16 + (lane >> 4) * 8);
                ldm_x4_trans(b0, b1, b2, b3, baddr);
                mma16816(d[2 * jp],     a0, a1, a2, a3, b0, b1);
                mma16816(d[2 * jp + 1], a0, a1, a2, a3, b2, b3);
            }
        }
        if (kc0 + 64 < K) __syncthreads();
    }

    // --- epilogue: bias + fp16 store ---
    int r  = lane >> 2;
    int cb = (lane & 3) * 2;
    int node_lo = node0 + warp * 16 + r;
    int node_hi = node_lo + 8;
#pragma unroll
    for (int j = 0; j < 8; j++) {
        float bx = __ldg(bg + 8 * j + cb);
        float by = __ldg(bg + 8 * j + cb + 1);
        __half2 lo = __floats2half2_rn(d[j][0] + bx, d[j][1] + by);
        __half2 hi = __floats2half2_rn(d[j][2] + bx, d[j][3] + by);
        if (node_lo < n_nodes)
            *reinterpret_cast<__half2*>(out + (size_t)node_lo * HID + 8 * j + cb) = lo;
        if (node_hi < n_nodes)
            *reinterpret_cast<__half2*>(out + (size_t)node_hi * HID + 8 * j + cb) = hi;
    }
}

// ---------------------------------------------------------------------------
// Pull-side aggregate over buckets: 32 lanes per node, split-K over chunks.
// ---------------------------------------------------------------------------
template <bool DO_LEAKY, bool FP16_OUT>
__global__ __launch_bounds__(256)
void aggregate_kernel(const uint2* __restrict__ Whh,
                      const int2* __restrict__ bucket,
                      const int* __restrict__ cnt,
                      void* __restrict__ outv,
                      int n_nodes) {
    int gid = blockIdx.x * blockDim.x + threadIdx.x;
    int node = gid >> 5;
    int lane32 = gid & 31;
    int half = lane32 >> 4;
    int c4 = lane32 & 15;
    if (node >= n_nodes) return;

    int degi = min(__ldg(cnt + node), BCAP);
    float deg = (float)degi;
    const int2* bk = bucket + (size_t)node * BCAP;

    float4 acc = make_float4(0.f, 0.f, 0.f, 0.f);

    for (int e = half * 8; e < degi; e += 16) {
        int2 c[8];
#pragma unroll
        for (int j = 0; j < 8; j++)
            c[j] = __ldg(bk + min(e + j, degi - 1));

        uint2 v[8];
#pragma unroll
        for (int j = 0; j < 8; j++)
            v[j] = __ldg(Whh + (size_t)c[j].x * 16 + c4);

#pragma unroll
        for (int j = 0; j < 8; j++) {
            float w = (e + j < degi) ? __int_as_float(c[j].y) : 0.f;
            float2 lo = __half22float2(*reinterpret_cast<__half2*>(&v[j].x));
            float2 hi = __half22float2(*reinterpret_cast<__half2*>(&v[j].y));
            acc.x += lo.x * w;
            acc.y += lo.y * w;
            acc.z += hi.x * w;
            acc.w += hi.y * w;
        }
    }

    acc.x += __shfl_xor_sync(0xffffffffu, acc.x, 16);
    acc.y += __shfl_xor_sync(0xffffffffu, acc.y, 16);
    acc.z += __shfl_xor_sync(0xffffffffu, acc.z, 16);
    acc.w += __shfl_xor_sync(0xffffffffu, acc.w, 16);

    if (half == 0) {
        float inv = 1.0f / fmaxf(deg, 1.0f);
        acc.x *= inv; acc.y *= inv; acc.z *= inv; acc.w *= inv;
        if (DO_LEAKY) {
            acc.x = leaky(acc.x); acc.y = leaky(acc.y);
            acc.z = leaky(acc.z); acc.w = leaky(acc.w);
        }
        if (FP16_OUT) {
            uint2 p;
            *reinterpret_cast<__half2*>(&p.x) = __floats2half2_rn(acc.x, acc.y);
            *reinterpret_cast<__half2*>(&p.y) = __floats2half2_rn(acc.z, acc.w);
            reinterpret_cast<uint2*>(outv)[(size_t)node * 16 + c4] = p;
        } else {
            reinterpret_cast<float4*>(outv)[(size_t)node * 16 + c4] = acc;
        }
    }
}

// ---------------------------------------------------------------------------
// Launch: bucket build forked onto side stream, overlapped with layer-1 GEMM.
// ---------------------------------------------------------------------------
extern "C" void kernel_launch(void* const* d_in, const int* in_sizes, int n_in,
                              void* d_out, int out_size) {
    const float* x   = (const float*)d_in[0];
    const float* ew  = (const float*)d_in[1];
    const float* W1  = (const float*)d_in[2];
    const float* b1  = (const float*)d_in[3];
    const float* W2  = (const float*)d_in[4];
    const float* b2  = (const float*)d_in[5];
    const int*   src = (const int*)d_in[6];
    const int*   dst = (const int*)d_in[7];
    float*       out = (float*)d_out;

    int n_nodes = in_sizes[0] / 128;
    int n_edges = in_sizes[1];

    void *pWh_v, *pH1_v, *pCnt_v, *pBk_v;
    cudaGetSymbolAddress(&pWh_v, g_Wh);
    cudaGetSymbolAddress(&pH1_v, g_h1);
    cudaGetSymbolAddress(&pCnt_v, g_cnt);
    cudaGetSymbolAddress(&pBk_v, g_bucket);
    __half* pWh = (__half*)pWh_v;
    __half* pH1 = (__half*)pH1_v;
    int*    pCnt = (int*)pCnt_v;
    int2*   pBk  = (int2*)pBk_v;

    int eb = (n_edges + 255) / 256;
    int gemm_blocks = (n_nodes + TILE_M - 1) / TILE_M;
    int agg_blocks = (n_nodes * 32 + 255) / 256;

    // Fork: side stream builds buckets while main stream runs gemm128.
    cudaEventRecord(g_ev_fork, 0);
    cudaStreamWaitEvent(g_side, g_ev_fork, 0);
    cudaMemsetAsync(pCnt, 0, (size_t)n_nodes * sizeof(int), g_side);
    fill_bucket_kernel<<<eb, 256, 0, g_side>>>(src, dst, ew, pCnt, pBk, n_edges);
    cudaEventRecord(g_ev_join, g_side);

    // Main: layer-1 projection (concurrent with bucket build)
    gemm_mma_kernel<128, false><<<gemm_blocks, 256>>>(x, W1, b1, pWh, n_nodes);
    cudaStreamWaitEvent(0, g_ev_join, 0);

    // Layer 1 aggregate -> h1 (fp16, leaky fused)
    aggregate_kernel<true, true><<<agg_blocks, 256>>>(
        (const uint2*)pWh, pBk, pCnt, pH1, n_nodes);

    // Layer 2
    gemm_mma_kernel<64, true><<<gemm_blocks, 256>>>(pH1, W2, b2, pWh, n_nodes);
    aggregate_kernel<false, false><<<agg_blocks, 256>>>(
        (const uint2*)pWh, pBk, pCnt, out, n_nodes);
}